// round 5
// baseline (speedup 1.0000x reference)
#include <cuda_runtime.h>
#include <math.h>

// Problem constants
#define B_    32
#define C_    256
#define CR_   64
#define HW_   12544            // 112*112 floats per channel
#define HALF_ 6272             // floats per half-channel
#define NCH   (B_*C_)          // 8192 channels

// Persistent-kernel geometry
#define GRID  296              // 2 CTAs/SM on 148 SMs -> co-residency guaranteed
#define TPB   256
#define NBP   8                // batches per phase (8 * 12.8MB = 102.8MB < 126MB L2)
#define NPH   (B_/NBP)         // 4 phases
#define CHP   (NBP*C_)         // 2048 channels per phase
#define UNITS (CHP*2)          // 4096 half-channel work units per phase

// Scratch
__device__ float    g_part[NCH * 2];   // per-half-channel raw sums
__device__ unsigned g_bar;             // grid barrier counter

struct F8 { float4 a, b; };

// 32-byte L2 evict-last load (sm_103 requires v8.b32 with L2:: modifiers)
__device__ __forceinline__ F8 ld_evict_last8(const float* p) {
    unsigned r0,r1,r2,r3,r4,r5,r6,r7;
    asm("ld.global.L2::evict_last.v8.b32 {%0,%1,%2,%3,%4,%5,%6,%7}, [%8];"
        : "=r"(r0),"=r"(r1),"=r"(r2),"=r"(r3),
          "=r"(r4),"=r"(r5),"=r"(r6),"=r"(r7) : "l"(p));
    F8 v;
    v.a.x = __uint_as_float(r0); v.a.y = __uint_as_float(r1);
    v.a.z = __uint_as_float(r2); v.a.w = __uint_as_float(r3);
    v.b.x = __uint_as_float(r4); v.b.y = __uint_as_float(r5);
    v.b.z = __uint_as_float(r6); v.b.w = __uint_as_float(r7);
    return v;
}

__global__ void init_kernel() { g_bar = 0u; }

__device__ __forceinline__ void grid_barrier(unsigned target) {
    __syncthreads();
    __threadfence();
    if (threadIdx.x == 0) {
        atomicAdd(&g_bar, 1u);
        while (*((volatile unsigned*)&g_bar) < target) __nanosleep(64);
    }
    __syncthreads();
}

__global__ __launch_bounds__(TPB, 2) void se_persistent(
    const float* __restrict__ x,
    const float* __restrict__ w1, const float* __restrict__ b1,
    const float* __restrict__ w2, const float* __restrict__ b2,
    float* __restrict__ out) {

    const int t = threadIdx.x;
    __shared__ float red[8];
    __shared__ float gap_s[CHP];    // 8 KB: pooled means, this phase
    __shared__ float h_s[NBP*CR_];  // 2 KB: hidden layer, this phase
    __shared__ float gate_s[CHP];   // 8 KB: gates, this phase

    for (int phase = 0; phase < NPH; ++phase) {
        const int ch0 = phase * CHP;   // first global channel of this phase

        // ---- Stage 1: GAP over this phase's 8 batches (pin x slab in L2) ----
        for (int u = blockIdx.x; u < UNITS; u += GRID) {
            const int bc = ch0 + (u >> 1);
            const float* __restrict__ base =
                x + (size_t)bc * HW_ + (size_t)(u & 1) * HALF_;

            // 784 F8 per half-channel = 3*256 + 16
            F8 v[3];
            #pragma unroll
            for (int k = 0; k < 3; ++k)
                v[k] = ld_evict_last8(base + (t + k * 256) * 8);
            F8 vt;
            if (t < 16) vt = ld_evict_last8(base + (t + 768) * 8);

            float sum = 0.0f;
            #pragma unroll
            for (int k = 0; k < 3; ++k)
                sum += ((v[k].a.x + v[k].a.y) + (v[k].a.z + v[k].a.w))
                     + ((v[k].b.x + v[k].b.y) + (v[k].b.z + v[k].b.w));
            if (t < 16)
                sum += ((vt.a.x + vt.a.y) + (vt.a.z + vt.a.w))
                     + ((vt.b.x + vt.b.y) + (vt.b.z + vt.b.w));

            #pragma unroll
            for (int o = 16; o > 0; o >>= 1)
                sum += __shfl_xor_sync(0xFFFFFFFFu, sum, o);
            if ((t & 31) == 0) red[t >> 5] = sum;
            __syncthreads();
            if (t == 0) {
                float tot = ((red[0]+red[1])+(red[2]+red[3]))
                          + ((red[4]+red[5])+(red[6]+red[7]));
                g_part[(size_t)bc * 2 + (u & 1)] = tot;
            }
            __syncthreads();
        }

        // ---- Grid barrier: all g_part of this phase visible ----
        grid_barrier((unsigned)(GRID * (phase + 1)));

        // ---- Stage 2: redundant per-CTA FC (gates for all 2048 channels) ----
        #pragma unroll
        for (int i = 0; i < NBP; ++i) {
            const int c = t + i * 256;
            const int bc = ch0 + c;
            gap_s[c] = (g_part[(size_t)bc*2] + g_part[(size_t)bc*2+1])
                       * (1.0f / (float)HW_);
        }
        __syncthreads();

        // hidden: 512 units (8 batches x 64)
        #pragma unroll
        for (int i = 0; i < 2; ++i) {
            const int idx = t + i * 256;
            const int b = idx >> 6, o = idx & 63;
            float acc = b1[o];
            const float* __restrict__ w = w1 + o * C_;
            const float* __restrict__ gp = gap_s + b * C_;
            #pragma unroll 8
            for (int c = 0; c < C_; ++c) acc = fmaf(gp[c], w[c], acc);
            h_s[idx] = fmaxf(acc, 0.0f);
        }
        __syncthreads();

        // gates: 2048 (8 batches x 256)
        #pragma unroll
        for (int i = 0; i < NBP; ++i) {
            const int idx = t + i * 256;
            const int b = idx >> 8, c = idx & 255;
            float acc = b2[c];
            const float* __restrict__ w = w2 + c * CR_;
            const float* __restrict__ hp = h_s + b * CR_;
            #pragma unroll 8
            for (int o = 0; o < CR_; ++o) acc = fmaf(hp[o], w[o], acc);
            gate_s[idx] = 1.0f / (1.0f + __expf(-acc));
        }
        __syncthreads();

        // ---- Stage 3: scale this phase's slab (reads hit L2) ----
        for (int u = blockIdx.x; u < UNITS; u += GRID) {
            const int ch = u >> 1;
            const int bc = ch0 + ch;
            const float g = gate_s[ch];
            const size_t off = (size_t)bc * HW_ + (size_t)(u & 1) * HALF_;
            const float4* __restrict__ xp =
                reinterpret_cast<const float4*>(x + off);
            float4* __restrict__ op = reinterpret_cast<float4*>(out + off);

            // 1568 float4 per half-channel = 6*256 + 32
            float4 v[6];
            #pragma unroll
            for (int k = 0; k < 6; ++k)
                v[k] = __ldcs(xp + t + k * 256);
            float4 vt;
            if (t < 32) vt = __ldcs(xp + t + 6 * 256);

            #pragma unroll
            for (int k = 0; k < 6; ++k) {
                v[k].x *= g; v[k].y *= g; v[k].z *= g; v[k].w *= g;
                __stcs(op + t + k * 256, v[k]);
            }
            if (t < 32) {
                vt.x *= g; vt.y *= g; vt.z *= g; vt.w *= g;
                __stcs(op + t + 6 * 256, vt);
            }
        }
        __syncthreads();   // reuse of smem next phase
    }
}

// ---------------------------------------------------------------------------
extern "C" void kernel_launch(void* const* d_in, const int* in_sizes, int n_in,
                              void* d_out, int out_size) {
    const float* x  = (const float*)d_in[0];
    const float* w1 = (const float*)d_in[1];
    const float* b1 = (const float*)d_in[2];
    const float* w2 = (const float*)d_in[3];
    const float* b2 = (const float*)d_in[4];
    float* out = (float*)d_out;

    init_kernel<<<1, 1>>>();
    se_persistent<<<GRID, TPB>>>(x, w1, b1, w2, b2, out);
}

// round 6
// speedup vs baseline: 7.2279x; 7.2279x over previous
#include <cuda_runtime.h>
#include <math.h>

// Problem constants
#define B_    32
#define C_    256
#define CR_   64
#define HW_   12544            // 112*112 floats per channel
#define NCH   (B_*C_)          // 8192 channels

// Phase geometry: 8 batches/phase = 102.8 MB slab, fits in 126 MB L2
#define NBP   8
#define NPH   (B_/NBP)         // 4 phases
#define CHP   (NBP*C_)         // 2048 channels per phase

// v8 (32B) load tiling: 12544/8 = 1568 = 6*256 + 32
#define NF8   6
#define NT8   32
// float4 tiling: 3136 = 12*256 + 64
#define NF4   12
#define NT4   64

__device__ float g_gap[NCH];
__device__ float g_gate[NCH];

struct F8 { float4 a, b; };

// 32-byte L2 evict-last load (sm_103 requires v8.b32 with L2:: modifiers)
__device__ __forceinline__ F8 ld_evict_last8(const float* p) {
    unsigned r0,r1,r2,r3,r4,r5,r6,r7;
    asm("ld.global.L2::evict_last.v8.b32 {%0,%1,%2,%3,%4,%5,%6,%7}, [%8];"
        : "=r"(r0),"=r"(r1),"=r"(r2),"=r"(r3),
          "=r"(r4),"=r"(r5),"=r"(r6),"=r"(r7) : "l"(p));
    F8 v;
    v.a.x = __uint_as_float(r0); v.a.y = __uint_as_float(r1);
    v.a.z = __uint_as_float(r2); v.a.w = __uint_as_float(r3);
    v.b.x = __uint_as_float(r4); v.b.y = __uint_as_float(r5);
    v.b.z = __uint_as_float(r6); v.b.w = __uint_as_float(r7);
    return v;
}

// ---------------------------------------------------------------------------
// Phase kernel 1: GAP for one 8-batch slab; pins the slab in L2 (evict_last).
// One CTA per channel.
// ---------------------------------------------------------------------------
__global__ __launch_bounds__(256) void gap_phase(const float* __restrict__ x,
                                                 int ch0) {
    const int bc = ch0 + blockIdx.x;
    const int t  = threadIdx.x;
    const float* __restrict__ base = x + (size_t)bc * HW_;

    F8 v[NF8];
    #pragma unroll
    for (int k = 0; k < NF8; ++k)
        v[k] = ld_evict_last8(base + (t + k * 256) * 8);
    F8 vt;
    if (t < NT8) vt = ld_evict_last8(base + (t + NF8 * 256) * 8);

    float sum = 0.0f;
    #pragma unroll
    for (int k = 0; k < NF8; ++k)
        sum += ((v[k].a.x + v[k].a.y) + (v[k].a.z + v[k].a.w))
             + ((v[k].b.x + v[k].b.y) + (v[k].b.z + v[k].b.w));
    if (t < NT8)
        sum += ((vt.a.x + vt.a.y) + (vt.a.z + vt.a.w))
             + ((vt.b.x + vt.b.y) + (vt.b.z + vt.b.w));

    #pragma unroll
    for (int o = 16; o > 0; o >>= 1)
        sum += __shfl_xor_sync(0xFFFFFFFFu, sum, o);

    __shared__ float s[8];
    if ((t & 31) == 0) s[t >> 5] = sum;
    __syncthreads();
    if (t < 8) {
        sum = s[t];
        #pragma unroll
        for (int o = 4; o > 0; o >>= 1)
            sum += __shfl_xor_sync(0xFFu, sum, o);
        if (t == 0)
            g_gap[bc] = sum * (1.0f / (float)HW_);
    }
}

// ---------------------------------------------------------------------------
// Phase kernel 2: MLP + sigmoid for 8 batches. One CTA per batch.
// ---------------------------------------------------------------------------
__global__ __launch_bounds__(256) void fc_phase(
    const float* __restrict__ w1, const float* __restrict__ b1,
    const float* __restrict__ w2, const float* __restrict__ b2,
    int b0) {
    const int b = b0 + blockIdx.x;
    __shared__ float gap_s[C_];
    __shared__ float h_s[CR_];

    gap_s[threadIdx.x] = g_gap[b * C_ + threadIdx.x];
    __syncthreads();

    if (threadIdx.x < CR_) {
        float acc = b1[threadIdx.x];
        const float* __restrict__ w = w1 + threadIdx.x * C_;
        #pragma unroll 8
        for (int c = 0; c < C_; ++c) acc = fmaf(gap_s[c], w[c], acc);
        h_s[threadIdx.x] = fmaxf(acc, 0.0f);
    }
    __syncthreads();

    float acc = b2[threadIdx.x];
    const float* __restrict__ w = w2 + threadIdx.x * CR_;
    #pragma unroll 8
    for (int o = 0; o < CR_; ++o) acc = fmaf(h_s[o], w[o], acc);
    g_gate[b * C_ + threadIdx.x] = 1.0f / (1.0f + __expf(-acc));
}

// ---------------------------------------------------------------------------
// Phase kernel 3: out = x * gate for the slab pinned by gap_phase.
// Reads hit L2 (ldcs = hit-and-demote), stores stream out (stcs).
// ---------------------------------------------------------------------------
__global__ __launch_bounds__(256) void scale_phase(
    const float* __restrict__ x, float* __restrict__ out, int ch0) {
    const int bc = ch0 + blockIdx.x;
    const int t  = threadIdx.x;
    const float g = g_gate[bc];
    const float4* __restrict__ xp =
        reinterpret_cast<const float4*>(x + (size_t)bc * HW_);
    float4* __restrict__ op =
        reinterpret_cast<float4*>(out + (size_t)bc * HW_);

    float4 v[NF4];
    #pragma unroll
    for (int k = 0; k < NF4; ++k)
        v[k] = __ldcs(xp + t + k * 256);
    float4 vt;
    if (t < NT4) vt = __ldcs(xp + t + NF4 * 256);

    #pragma unroll
    for (int k = 0; k < NF4; ++k) {
        v[k].x *= g; v[k].y *= g; v[k].z *= g; v[k].w *= g;
        __stcs(op + t + k * 256, v[k]);
    }
    if (t < NT4) {
        vt.x *= g; vt.y *= g; vt.z *= g; vt.w *= g;
        __stcs(op + t + NF4 * 256, vt);
    }
}

// ---------------------------------------------------------------------------
// Launch: 4 phases x (gap -> fc -> scale); launch boundaries are the barriers.
// ---------------------------------------------------------------------------
extern "C" void kernel_launch(void* const* d_in, const int* in_sizes, int n_in,
                              void* d_out, int out_size) {
    const float* x  = (const float*)d_in[0];
    const float* w1 = (const float*)d_in[1];
    const float* b1 = (const float*)d_in[2];
    const float* w2 = (const float*)d_in[3];
    const float* b2 = (const float*)d_in[4];
    float* out = (float*)d_out;

    for (int p = 0; p < NPH; ++p) {
        const int ch0 = p * CHP;
        const int b0  = p * NBP;
        gap_phase<<<CHP, 256>>>(x, ch0);
        fc_phase<<<NBP, 256>>>(w1, b1, w2, b2, b0);
        scale_phase<<<CHP, 256>>>(x, out, ch0);
    }
}

// round 7
// speedup vs baseline: 9.9181x; 1.3722x over previous
#include <cuda_runtime.h>
#include <math.h>

// Problem constants
#define B_    32
#define C_    256
#define CR_   64
#define HW_   12544       // 112*112
#define NCH   (B_*C_)     // 8192 channels
#define KEEP  2048        // tail channels pinned in L2 between pass 1 and 2 (~103 MB)

// v8 (32B) tiling: 12544/8 = 1568 = 6*256 + 32
#define NF8   6
#define NT8   32
// float4 tiling: 3136 = 12*256 + 64
#define NF4   12
#define NT4   64

__device__ float g_gap[NCH];
__device__ float g_gate[NCH];

struct F8 { float4 a, b; };

__device__ __forceinline__ F8 ld_evict_last8(const float* p) {
    unsigned r0,r1,r2,r3,r4,r5,r6,r7;
    asm("ld.global.L2::evict_last.v8.b32 {%0,%1,%2,%3,%4,%5,%6,%7}, [%8];"
        : "=r"(r0),"=r"(r1),"=r"(r2),"=r"(r3),
          "=r"(r4),"=r"(r5),"=r"(r6),"=r"(r7) : "l"(p));
    F8 v;
    v.a.x = __uint_as_float(r0); v.a.y = __uint_as_float(r1);
    v.a.z = __uint_as_float(r2); v.a.w = __uint_as_float(r3);
    v.b.x = __uint_as_float(r4); v.b.y = __uint_as_float(r5);
    v.b.z = __uint_as_float(r6); v.b.w = __uint_as_float(r7);
    return v;
}

__device__ __forceinline__ F8 ld_evict_first8(const float* p) {
    unsigned r0,r1,r2,r3,r4,r5,r6,r7;
    asm("ld.global.L2::evict_first.v8.b32 {%0,%1,%2,%3,%4,%5,%6,%7}, [%8];"
        : "=r"(r0),"=r"(r1),"=r"(r2),"=r"(r3),
          "=r"(r4),"=r"(r5),"=r"(r6),"=r"(r7) : "l"(p));
    F8 v;
    v.a.x = __uint_as_float(r0); v.a.y = __uint_as_float(r1);
    v.a.z = __uint_as_float(r2); v.a.w = __uint_as_float(r3);
    v.b.x = __uint_as_float(r4); v.b.y = __uint_as_float(r5);
    v.b.z = __uint_as_float(r6); v.b.w = __uint_as_float(r7);
    return v;
}

// ---------------------------------------------------------------------------
// Kernel 1: global average pool. One CTA per (b,c) channel. 32B loads.
// Early channels stream (evict_first); last KEEP channels pinned (evict_last).
// ---------------------------------------------------------------------------
__global__ __launch_bounds__(256) void gap_kernel(const float* __restrict__ x) {
    const int bc = blockIdx.x;
    const int t  = threadIdx.x;
    const float* __restrict__ base = x + (size_t)bc * HW_;
    const bool keep = (bc >= NCH - KEEP);

    F8 v[NF8];
    F8 vt;
    if (keep) {
        #pragma unroll
        for (int k = 0; k < NF8; ++k)
            v[k] = ld_evict_last8(base + (t + k * 256) * 8);
        if (t < NT8) vt = ld_evict_last8(base + (t + NF8 * 256) * 8);
    } else {
        #pragma unroll
        for (int k = 0; k < NF8; ++k)
            v[k] = ld_evict_first8(base + (t + k * 256) * 8);
        if (t < NT8) vt = ld_evict_first8(base + (t + NF8 * 256) * 8);
    }

    float sum = 0.0f;
    #pragma unroll
    for (int k = 0; k < NF8; ++k)
        sum += ((v[k].a.x + v[k].a.y) + (v[k].a.z + v[k].a.w))
             + ((v[k].b.x + v[k].b.y) + (v[k].b.z + v[k].b.w));
    if (t < NT8)
        sum += ((vt.a.x + vt.a.y) + (vt.a.z + vt.a.w))
             + ((vt.b.x + vt.b.y) + (vt.b.z + vt.b.w));

    #pragma unroll
    for (int o = 16; o > 0; o >>= 1)
        sum += __shfl_xor_sync(0xFFFFFFFFu, sum, o);

    __shared__ float s[8];
    if ((t & 31) == 0) s[t >> 5] = sum;
    __syncthreads();
    if (t < 8) {
        sum = s[t];
        #pragma unroll
        for (int o = 4; o > 0; o >>= 1)
            sum += __shfl_xor_sync(0xFFu, sum, o);
        if (t == 0)
            g_gap[bc] = sum * (1.0f / (float)HW_);
    }
}

// ---------------------------------------------------------------------------
// Kernel 2: tiny 2-layer MLP + sigmoid gate. One CTA per batch sample.
// ---------------------------------------------------------------------------
__global__ __launch_bounds__(256) void se_fc_kernel(
    const float* __restrict__ w1, const float* __restrict__ b1,
    const float* __restrict__ w2, const float* __restrict__ b2) {
    const int b = blockIdx.x;
    __shared__ float gap_s[C_];
    __shared__ float h_s[CR_];

    gap_s[threadIdx.x] = g_gap[b * C_ + threadIdx.x];
    __syncthreads();

    if (threadIdx.x < CR_) {
        float acc = b1[threadIdx.x];
        const float* __restrict__ w = w1 + threadIdx.x * C_;
        #pragma unroll 8
        for (int c = 0; c < C_; ++c) acc = fmaf(gap_s[c], w[c], acc);
        h_s[threadIdx.x] = fmaxf(acc, 0.0f);
    }
    __syncthreads();

    float acc = b2[threadIdx.x];
    const float* __restrict__ w = w2 + threadIdx.x * CR_;
    #pragma unroll 8
    for (int o = 0; o < CR_; ++o) acc = fmaf(h_s[o], w[o], acc);
    g_gate[b * C_ + threadIdx.x] = 1.0f / (1.0f + __expf(-acc));
}

// ---------------------------------------------------------------------------
// Kernel 3: out = x * gate[bc]. Reverse channel order (pinned tail first).
// __ldlu = last-use read: demotes/releases L2 lines as consumed, freeing
// victims for the store stream. __stcs streaming stores.
// ---------------------------------------------------------------------------
__global__ __launch_bounds__(256) void scale_kernel(
    const float* __restrict__ x, float* __restrict__ out) {
    const int bc = NCH - 1 - blockIdx.x;     // reverse order
    const int t  = threadIdx.x;
    const float g = g_gate[bc];
    const float4* __restrict__ xp =
        reinterpret_cast<const float4*>(x + (size_t)bc * HW_);
    float4* __restrict__ op =
        reinterpret_cast<float4*>(out + (size_t)bc * HW_);

    float4 v[NF4];
    #pragma unroll
    for (int k = 0; k < NF4; ++k)
        v[k] = __ldlu(xp + t + k * 256);
    float4 vt;
    if (t < NT4) vt = __ldlu(xp + t + NF4 * 256);

    #pragma unroll
    for (int k = 0; k < NF4; ++k) {
        v[k].x *= g; v[k].y *= g; v[k].z *= g; v[k].w *= g;
        __stcs(op + t + k * 256, v[k]);
    }
    if (t < NT4) {
        vt.x *= g; vt.y *= g; vt.z *= g; vt.w *= g;
        __stcs(op + t + NF4 * 256, vt);
    }
}

// ---------------------------------------------------------------------------
extern "C" void kernel_launch(void* const* d_in, const int* in_sizes, int n_in,
                              void* d_out, int out_size) {
    const float* x  = (const float*)d_in[0];
    const float* w1 = (const float*)d_in[1];
    const float* b1 = (const float*)d_in[2];
    const float* w2 = (const float*)d_in[3];
    const float* b2 = (const float*)d_in[4];
    float* out = (float*)d_out;

    gap_kernel<<<NCH, 256>>>(x);
    se_fc_kernel<<<B_, 256>>>(w1, b1, w2, b2);
    scale_kernel<<<NCH, 256>>>(x, out);
}